// round 3
// baseline (speedup 1.0000x reference)
#include <cuda_runtime.h>

#define EPS_W  1e-8f
#define EPS_LN 1e-5f
#define NROWS  1028   // 64 + 256 + 512 + 128 + 64 + 4
#define DOUT   256

// Precomputed fused table: P[row][o] = sum_k E_t[v][k] * w_q[o, 16*t+k]
// (bias folded into the result_class slice, rows 1024..1027)
__device__ float g_P[NROWS * DOUT];
__device__ float g_scale;
__device__ int   g_stride;   // 2 if indices are int64 (read low words), 1 if int32

// ---------------------------------------------------------------------------
// Detect index dtype: view event_type as int32 words. If the buffer is int64
// (little-endian, values < 64), every odd word is 0. If int32, odd words are
// random indices (P(all 256 == 0) = (1/64)^256 ~ 0).
__global__ void k_detect(const int* __restrict__ ev) {
    __shared__ int any;
    if (threadIdx.x == 0) any = 0;
    __syncthreads();
    int nz = 0;
    for (int i = threadIdx.x; i < 256; i += blockDim.x)
        if (ev[2 * i + 1] != 0) nz = 1;
    if (nz) atomicOr(&any, 1);
    __syncthreads();
    if (threadIdx.x == 0) g_stride = any ? 1 : 2;
}

// ---------------------------------------------------------------------------
// scale = mean(|W|) over 256*96 = 24576 elements
__global__ void k_scale(const float* __restrict__ W) {
    __shared__ float red[32];
    int tid = threadIdx.x;  // 1024 threads
    float s = 0.f;
    for (int i = tid; i < 24576; i += 1024) s += fabsf(W[i]);
    #pragma unroll
    for (int o = 16; o > 0; o >>= 1) s += __shfl_xor_sync(~0u, s, o);
    if ((tid & 31) == 0) red[tid >> 5] = s;
    __syncthreads();
    if (tid < 32) {
        float v = red[tid];
        #pragma unroll
        for (int o = 16; o > 0; o >>= 1) v += __shfl_xor_sync(~0u, v, o);
        if (tid == 0) g_scale = v / 24576.0f;
    }
}

// ---------------------------------------------------------------------------
// Build P: one block per row (table entry), 256 threads = output channels.
__global__ void k_build(const float* __restrict__ W, const float* __restrict__ bias,
                        const float* __restrict__ E_et, const float* __restrict__ E_fc,
                        const float* __restrict__ E_sc, const float* __restrict__ E_of,
                        const float* __restrict__ E_tt, const float* __restrict__ E_rc) {
    int r = blockIdx.x, o = threadIdx.x;
    float scale = g_scale;
    float inv = 1.0f / (scale + EPS_W);
    const float* E; int t, v;
    if      (r < 64)   { t = 0; v = r;        E = E_et; }
    else if (r < 320)  { t = 1; v = r - 64;   E = E_fc; }
    else if (r < 832)  { t = 2; v = r - 320;  E = E_sc; }
    else if (r < 960)  { t = 3; v = r - 832;  E = E_of; }
    else if (r < 1024) { t = 4; v = r - 960;  E = E_tt; }
    else               { t = 5; v = r - 1024; E = E_rc; }
    float acc = (t == 5) ? bias[o] : 0.0f;   // fold bias into the tiny rc table
    #pragma unroll
    for (int k = 0; k < 16; k++) {
        float w = W[o * 96 + t * 16 + k];
        float q = rintf(w * inv);                 // round-half-to-even == jnp.round
        q = fminf(1.0f, fmaxf(-1.0f, q));
        acc = fmaf(E[v * 16 + k], q * scale, acc);
    }
    g_P[r * DOUT + o] = acc;
}

// ---------------------------------------------------------------------------
__device__ __forceinline__ float4 f4add(float4 a, float4 b) {
    a.x += b.x; a.y += b.y; a.z += b.z; a.w += b.w; return a;
}

// Main: one warp per token. Thread `lane` owns outputs [lane*4, lane*4+4) and
// [128 + lane*4, ...) as two float4 lanes. All reductions via warp shuffles.
__global__ void __launch_bounds__(256) k_main(
    const int* __restrict__ i0, const int* __restrict__ i1,
    const int* __restrict__ i2, const int* __restrict__ i3,
    const int* __restrict__ i4, const int* __restrict__ i5,
    const float* __restrict__ gamma, const float* __restrict__ beta,
    float* __restrict__ out, int ntok)
{
    const float4* __restrict__ P4 = (const float4*)g_P;  // 64 float4 per row
    int lane  = threadIdx.x & 31;
    int warp  = blockIdx.x * (blockDim.x >> 5) + (threadIdx.x >> 5);
    int nwarp = gridDim.x * (blockDim.x >> 5);
    int stride = g_stride;

    float4 gg0 = ((const float4*)gamma)[lane];
    float4 gg1 = ((const float4*)gamma)[lane + 32];
    float4 bb0 = ((const float4*)beta )[lane];
    float4 bb1 = ((const float4*)beta )[lane + 32];

    for (int t = warp; t < ntok; t += nwarp) {
        size_t ti = (size_t)t * (size_t)stride;
        int r0 = i0[ti];
        int r1 = i1[ti] + 64;
        int r2 = i2[ti] + 320;
        int r3 = i3[ti] + 832;
        int r4 = i4[ti] + 960;
        int r5 = i5[ti] + 1024;

        float4 z0 = P4[r0 * 64 + lane];
        float4 z1 = P4[r0 * 64 + 32 + lane];
        z0 = f4add(z0, P4[r1 * 64 + lane]);      z1 = f4add(z1, P4[r1 * 64 + 32 + lane]);
        z0 = f4add(z0, P4[r2 * 64 + lane]);      z1 = f4add(z1, P4[r2 * 64 + 32 + lane]);
        z0 = f4add(z0, P4[r3 * 64 + lane]);      z1 = f4add(z1, P4[r3 * 64 + 32 + lane]);
        z0 = f4add(z0, P4[r4 * 64 + lane]);      z1 = f4add(z1, P4[r4 * 64 + 32 + lane]);
        z0 = f4add(z0, P4[r5 * 64 + lane]);      z1 = f4add(z1, P4[r5 * 64 + 32 + lane]);

        float s  = z0.x + z0.y + z0.z + z0.w + z1.x + z1.y + z1.z + z1.w;
        float sq = z0.x*z0.x + z0.y*z0.y + z0.z*z0.z + z0.w*z0.w
                 + z1.x*z1.x + z1.y*z1.y + z1.z*z1.z + z1.w*z1.w;
        #pragma unroll
        for (int o = 16; o > 0; o >>= 1) {
            s  += __shfl_xor_sync(~0u, s,  o);
            sq += __shfl_xor_sync(~0u, sq, o);
        }
        float mu   = s * (1.0f / 256.0f);
        float var  = sq * (1.0f / 256.0f) - mu * mu;
        float rstd = rsqrtf(var + EPS_LN);

        float4* op = (float4*)(out + (size_t)t * DOUT);
        float4 o0, o1;
        o0.x = (z0.x - mu) * rstd * gg0.x + bb0.x;
        o0.y = (z0.y - mu) * rstd * gg0.y + bb0.y;
        o0.z = (z0.z - mu) * rstd * gg0.z + bb0.z;
        o0.w = (z0.w - mu) * rstd * gg0.w + bb0.w;
        o1.x = (z1.x - mu) * rstd * gg1.x + bb1.x;
        o1.y = (z1.y - mu) * rstd * gg1.y + bb1.y;
        o1.z = (z1.z - mu) * rstd * gg1.z + bb1.z;
        o1.w = (z1.w - mu) * rstd * gg1.w + bb1.w;
        __stcs(op + lane,      o0);   // streaming store: keep L2 for the table
        __stcs(op + 32 + lane, o1);
    }
}

// ---------------------------------------------------------------------------
extern "C" void kernel_launch(void* const* d_in, const int* in_sizes, int n_in,
                              void* d_out, int out_size) {
    // Inputs (metadata order):
    // 0..5 : event_type, fault_class, syscall_class, opcode_family,
    //        transition_type, result_class        [B,S] integer
    // 6..11: E_et[64,16] E_fc[256,16] E_sc[512,16] E_of[128,16] E_tt[64,16] E_rc[4,16]
    // 12: W[256,96]  13: b[256]  14: gamma[256]  15: beta[256]
    int ntok = in_sizes[0];

    k_detect<<<1, 256>>>((const int*)d_in[0]);
    k_scale<<<1, 1024>>>((const float*)d_in[12]);
    k_build<<<NROWS, 256>>>((const float*)d_in[12], (const float*)d_in[13],
                            (const float*)d_in[6], (const float*)d_in[7],
                            (const float*)d_in[8], (const float*)d_in[9],
                            (const float*)d_in[10], (const float*)d_in[11]);
    k_main<<<2048, 256>>>((const int*)d_in[0], (const int*)d_in[1],
                          (const int*)d_in[2], (const int*)d_in[3],
                          (const int*)d_in[4], (const int*)d_in[5],
                          (const float*)d_in[14], (const float*)d_in[15],
                          (float*)d_out, ntok);
}

// round 4
// speedup vs baseline: 1.2905x; 1.2905x over previous
#include <cuda_runtime.h>
#include <cuda_fp16.h>

#define EPS_W  1e-8f
#define EPS_LN 1e-5f
#define NROWS  1028   // 64 + 256 + 512 + 128 + 64 + 4
#define DOUT   256

// Precomputed fused table in fp16: P[row][o] = sum_k E_t[v][k] * w_q[o, 16*t+k]
// (bias folded into the result_class slice, rows 1024..1027)
__device__ __align__(16) __half g_Ph[NROWS * DOUT];
__device__ float g_scale;
__device__ int   g_stride;   // 2 if indices are int64 (read low words), 1 if int32

// ---------------------------------------------------------------------------
// Detect index dtype: view event_type as int32 words. If the buffer is int64
// (little-endian, values < 64), every odd word is 0. If int32, odd words are
// random indices (P(all 256 == 0) = (1/64)^256 ~ 0).
__global__ void k_detect(const int* __restrict__ ev) {
    __shared__ int any;
    if (threadIdx.x == 0) any = 0;
    __syncthreads();
    int nz = 0;
    for (int i = threadIdx.x; i < 256; i += blockDim.x)
        if (ev[2 * i + 1] != 0) nz = 1;
    if (nz) atomicOr(&any, 1);
    __syncthreads();
    if (threadIdx.x == 0) g_stride = any ? 1 : 2;
}

// ---------------------------------------------------------------------------
// scale = mean(|W|) over 256*96 = 24576 elements
__global__ void k_scale(const float* __restrict__ W) {
    __shared__ float red[32];
    int tid = threadIdx.x;  // 1024 threads
    float s = 0.f;
    for (int i = tid; i < 24576; i += 1024) s += fabsf(W[i]);
    #pragma unroll
    for (int o = 16; o > 0; o >>= 1) s += __shfl_xor_sync(~0u, s, o);
    if ((tid & 31) == 0) red[tid >> 5] = s;
    __syncthreads();
    if (tid < 32) {
        float v = red[tid];
        #pragma unroll
        for (int o = 16; o > 0; o >>= 1) v += __shfl_xor_sync(~0u, v, o);
        if (tid == 0) g_scale = v / 24576.0f;
    }
}

// ---------------------------------------------------------------------------
// Build P (fp16): one block per row (table entry), 256 threads = output channels.
__global__ void k_build(const float* __restrict__ W, const float* __restrict__ bias,
                        const float* __restrict__ E_et, const float* __restrict__ E_fc,
                        const float* __restrict__ E_sc, const float* __restrict__ E_of,
                        const float* __restrict__ E_tt, const float* __restrict__ E_rc) {
    int r = blockIdx.x, o = threadIdx.x;
    float scale = g_scale;
    float inv = 1.0f / (scale + EPS_W);
    const float* E; int t, v;
    if      (r < 64)   { t = 0; v = r;        E = E_et; }
    else if (r < 320)  { t = 1; v = r - 64;   E = E_fc; }
    else if (r < 832)  { t = 2; v = r - 320;  E = E_sc; }
    else if (r < 960)  { t = 3; v = r - 832;  E = E_of; }
    else if (r < 1024) { t = 4; v = r - 960;  E = E_tt; }
    else               { t = 5; v = r - 1024; E = E_rc; }
    float acc = (t == 5) ? bias[o] : 0.0f;   // fold bias into the tiny rc table
    #pragma unroll
    for (int k = 0; k < 16; k++) {
        float w = W[o * 96 + t * 16 + k];
        float q = rintf(w * inv);                 // round-half-to-even == jnp.round
        q = fminf(1.0f, fmaxf(-1.0f, q));
        acc = fmaf(E[v * 16 + k], q * scale, acc);
    }
    g_Ph[r * DOUT + o] = __float2half(acc);
}

// ---------------------------------------------------------------------------
__device__ __forceinline__ float4 f4add(float4 a, float4 b) {
    a.x += b.x; a.y += b.y; a.z += b.z; a.w += b.w; return a;
}
__device__ __forceinline__ float4 cvt4(uint2 q) {
    __half2 h0 = *(__half2*)&q.x;
    __half2 h1 = *(__half2*)&q.y;
    float2 f0 = __half22float2(h0);
    float2 f1 = __half22float2(h1);
    return make_float4(f0.x, f0.y, f1.x, f1.y);
}

// Main: one warp per token, 32-token tiles per warp iteration.
// Lane owns output cols [4*lane, +4) and [128+4*lane, +4).
// Table rows are fp16: row r = 64 uint2; lane reads uint2[lane] and uint2[lane+32].
__global__ void __launch_bounds__(256) k_main(
    const int* __restrict__ i0, const int* __restrict__ i1,
    const int* __restrict__ i2, const int* __restrict__ i3,
    const int* __restrict__ i4, const int* __restrict__ i5,
    const float* __restrict__ gamma, const float* __restrict__ beta,
    float* __restrict__ out, int ntok)
{
    const uint2* __restrict__ Pu = (const uint2*)g_Ph;   // 64 uint2 per row
    int lane  = threadIdx.x & 31;
    int warp  = blockIdx.x * (blockDim.x >> 5) + (threadIdx.x >> 5);
    int nwarp = gridDim.x * (blockDim.x >> 5);
    int stride = g_stride;

    float4 gg0 = ((const float4*)gamma)[lane];
    float4 gg1 = ((const float4*)gamma)[lane + 32];
    float4 bb0 = ((const float4*)beta )[lane];
    float4 bb1 = ((const float4*)beta )[lane + 32];

    int ntiles = (ntok + 31) >> 5;
    for (int tile = warp; tile < ntiles; tile += nwarp) {
        int t0 = tile << 5;
        int nt = min(32, ntok - t0);

        // Coalesced per-lane index loads for this tile (lane j -> token t0+j),
        // premultiplied to uint2 row offsets.
        int a0 = 0, a1 = 0, a2 = 0, a3 = 0, a4 = 0, a5 = 0;
        if (lane < nt) {
            size_t ti = (size_t)(t0 + lane) * (size_t)stride;
            a0 =  i0[ti]          * 64;
            a1 = (i1[ti] + 64)    * 64;
            a2 = (i2[ti] + 320)   * 64;
            a3 = (i3[ti] + 832)   * 64;
            a4 = (i4[ti] + 960)   * 64;
            a5 = (i5[ti] + 1024)  * 64;
        }

        for (int j = 0; j < nt; j++) {
            int b0 = __shfl_sync(~0u, a0, j);
            int b1 = __shfl_sync(~0u, a1, j);
            int b2 = __shfl_sync(~0u, a2, j);
            int b3 = __shfl_sync(~0u, a3, j);
            int b4 = __shfl_sync(~0u, a4, j);
            int b5 = __shfl_sync(~0u, a5, j);

            // Issue all 12 gathers up front for MLP.
            uint2 q0a = Pu[b0 + lane], q0b = Pu[b0 + 32 + lane];
            uint2 q1a = Pu[b1 + lane], q1b = Pu[b1 + 32 + lane];
            uint2 q2a = Pu[b2 + lane], q2b = Pu[b2 + 32 + lane];
            uint2 q3a = Pu[b3 + lane], q3b = Pu[b3 + 32 + lane];
            uint2 q4a = Pu[b4 + lane], q4b = Pu[b4 + 32 + lane];
            uint2 q5a = Pu[b5 + lane], q5b = Pu[b5 + 32 + lane];

            float4 z0 = cvt4(q0a);
            float4 z1 = cvt4(q0b);
            z0 = f4add(z0, cvt4(q1a));  z1 = f4add(z1, cvt4(q1b));
            z0 = f4add(z0, cvt4(q2a));  z1 = f4add(z1, cvt4(q2b));
            z0 = f4add(z0, cvt4(q3a));  z1 = f4add(z1, cvt4(q3b));
            z0 = f4add(z0, cvt4(q4a));  z1 = f4add(z1, cvt4(q4b));
            z0 = f4add(z0, cvt4(q5a));  z1 = f4add(z1, cvt4(q5b));

            float s  = z0.x + z0.y + z0.z + z0.w + z1.x + z1.y + z1.z + z1.w;
            float sq = z0.x*z0.x + z0.y*z0.y + z0.z*z0.z + z0.w*z0.w
                     + z1.x*z1.x + z1.y*z1.y + z1.z*z1.z + z1.w*z1.w;
            #pragma unroll
            for (int o = 16; o > 0; o >>= 1) {
                s  += __shfl_xor_sync(~0u, s,  o);
                sq += __shfl_xor_sync(~0u, sq, o);
            }
            float mu   = s * (1.0f / 256.0f);
            float var  = sq * (1.0f / 256.0f) - mu * mu;
            float rstd = rsqrtf(var + EPS_LN);

            float4* op = (float4*)(out + (size_t)(t0 + j) * DOUT);
            float4 o0, o1;
            o0.x = (z0.x - mu) * rstd * gg0.x + bb0.x;
            o0.y = (z0.y - mu) * rstd * gg0.y + bb0.y;
            o0.z = (z0.z - mu) * rstd * gg0.z + bb0.z;
            o0.w = (z0.w - mu) * rstd * gg0.w + bb0.w;
            o1.x = (z1.x - mu) * rstd * gg1.x + bb1.x;
            o1.y = (z1.y - mu) * rstd * gg1.y + bb1.y;
            o1.z = (z1.z - mu) * rstd * gg1.z + bb1.z;
            o1.w = (z1.w - mu) * rstd * gg1.w + bb1.w;
            __stcs(op + lane,      o0);   // streaming store: keep L2 for the table
            __stcs(op + 32 + lane, o1);
        }
    }
}

// ---------------------------------------------------------------------------
extern "C" void kernel_launch(void* const* d_in, const int* in_sizes, int n_in,
                              void* d_out, int out_size) {
    // Inputs (metadata order):
    // 0..5 : event_type, fault_class, syscall_class, opcode_family,
    //        transition_type, result_class        [B,S] integer
    // 6..11: E_et[64,16] E_fc[256,16] E_sc[512,16] E_of[128,16] E_tt[64,16] E_rc[4,16]
    // 12: W[256,96]  13: b[256]  14: gamma[256]  15: beta[256]
    int ntok = in_sizes[0];

    k_detect<<<1, 256>>>((const int*)d_in[0]);
    k_scale<<<1, 1024>>>((const float*)d_in[12]);
    k_build<<<NROWS, 256>>>((const float*)d_in[12], (const float*)d_in[13],
                            (const float*)d_in[6], (const float*)d_in[7],
                            (const float*)d_in[8], (const float*)d_in[9],
                            (const float*)d_in[10], (const float*)d_in[11]);
    k_main<<<2048, 256>>>((const int*)d_in[0], (const int*)d_in[1],
                          (const int*)d_in[2], (const int*)d_in[3],
                          (const int*)d_in[4], (const int*)d_in[5],
                          (const float*)d_in[14], (const float*)d_in[15],
                          (float*)d_out, ntok);
}

// round 5
// speedup vs baseline: 1.4618x; 1.1327x over previous
#include <cuda_runtime.h>
#include <cuda_fp16.h>

#define EPS_W  1e-8f
#define EPS_LN 1e-5f
// combined table rows: etrc(64*4=256) + fc(256) + sc(512) + of(128) + tt(64)
#define NROWS  1216
#define DOUT   256

// Fused, column-permuted fp16 table.
// Row r, physical half index 8*l+c  (l in [0,32), c in [0,8)):
//   c<4  -> logical output col 4*l+c
//   c>=4 -> logical output col 128 + 4*l + (c-4)
// So one uint4 load at offset 16B*l gives lane l exactly its 8 owned columns.
// Row blocks: [0,256)=etrc (bias folded), [256,512)=fc, [512,1024)=sc,
//             [1024,1152)=of, [1152,1216)=tt
__device__ __align__(16) __half g_Ph[NROWS * DOUT];
__device__ float g_scale;
__device__ int   g_stride;   // 2 if indices are int64 (read low words), 1 if int32

// ---------------------------------------------------------------------------
// Detect index dtype (int64 vs int32) by inspecting odd 32-bit words.
__global__ void k_detect(const int* __restrict__ ev) {
    __shared__ int any;
    if (threadIdx.x == 0) any = 0;
    __syncthreads();
    int nz = 0;
    for (int i = threadIdx.x; i < 256; i += blockDim.x)
        if (ev[2 * i + 1] != 0) nz = 1;
    if (nz) atomicOr(&any, 1);
    __syncthreads();
    if (threadIdx.x == 0) g_stride = any ? 1 : 2;
}

// ---------------------------------------------------------------------------
// scale = mean(|W|) over 256*96 elements
__global__ void k_scale(const float* __restrict__ W) {
    __shared__ float red[32];
    int tid = threadIdx.x;  // 1024 threads
    float s = 0.f;
    for (int i = tid; i < 24576; i += 1024) s += fabsf(W[i]);
    #pragma unroll
    for (int o = 16; o > 0; o >>= 1) s += __shfl_xor_sync(~0u, s, o);
    if ((tid & 31) == 0) red[tid >> 5] = s;
    __syncthreads();
    if (tid < 32) {
        float v = red[tid];
        #pragma unroll
        for (int o = 16; o > 0; o >>= 1) v += __shfl_xor_sync(~0u, v, o);
        if (tid == 0) g_scale = v / 24576.0f;
    }
}

// ---------------------------------------------------------------------------
__device__ __forceinline__ float qdot16(const float* __restrict__ E, int v,
                                        const float* __restrict__ W, int o,
                                        int t, float scale, float inv, float acc) {
    #pragma unroll
    for (int k = 0; k < 16; k++) {
        float w = W[o * 96 + t * 16 + k];
        float q = rintf(w * inv);                 // round-half-to-even == jnp.round
        q = fminf(1.0f, fmaxf(-1.0f, q));
        acc = fmaf(E[v * 16 + k], q * scale, acc);
    }
    return acc;
}

// Build permuted fp16 table: one block per row, 256 threads = output channels.
__global__ void k_build(const float* __restrict__ W, const float* __restrict__ bias,
                        const float* __restrict__ E_et, const float* __restrict__ E_fc,
                        const float* __restrict__ E_sc, const float* __restrict__ E_of,
                        const float* __restrict__ E_tt, const float* __restrict__ E_rc) {
    int r = blockIdx.x, o = threadIdx.x;
    float scale = g_scale;
    float inv = 1.0f / (scale + EPS_W);
    float acc;
    if (r < 256) {           // etrc: r = et*4 + rc ; fold bias here
        int v_et = r >> 2, v_rc = r & 3;
        acc = bias[o];
        acc = qdot16(E_et, v_et, W, o, 0, scale, inv, acc);
        acc = qdot16(E_rc, v_rc, W, o, 5, scale, inv, acc);
    } else if (r < 512) {    // fc
        acc = qdot16(E_fc, r - 256, W, o, 1, scale, inv, 0.0f);
    } else if (r < 1024) {   // sc
        acc = qdot16(E_sc, r - 512, W, o, 2, scale, inv, 0.0f);
    } else if (r < 1152) {   // of
        acc = qdot16(E_of, r - 1024, W, o, 3, scale, inv, 0.0f);
    } else {                 // tt
        acc = qdot16(E_tt, r - 1152, W, o, 4, scale, inv, 0.0f);
    }
    // permuted position
    int c = (o < 128) ? (((o >> 2) << 3) + (o & 3))
                      : ((((o - 128) >> 2) << 3) + 4 + ((o - 128) & 3));
    g_Ph[r * DOUT + c] = __float2half(acc);
}

// ---------------------------------------------------------------------------
__device__ __forceinline__ __half2 h2(unsigned u) { return *reinterpret_cast<__half2*>(&u); }

// Main: one warp per token, 32-token tiles; lane owns cols [4l,4l+4) and
// [128+4l, +4). 5 uint4 gathers/token, fp16 accumulation, fp32 LN.
__global__ void __launch_bounds__(256) k_main(
    const int* __restrict__ i0, const int* __restrict__ i1,
    const int* __restrict__ i2, const int* __restrict__ i3,
    const int* __restrict__ i4, const int* __restrict__ i5,
    const float* __restrict__ gamma, const float* __restrict__ beta,
    float* __restrict__ out, int ntok)
{
    const uint4* __restrict__ Pu = (const uint4*)g_Ph;   // 32 uint4 per row
    int lane  = threadIdx.x & 31;
    int warp  = blockIdx.x * (blockDim.x >> 5) + (threadIdx.x >> 5);
    int nwarp = gridDim.x * (blockDim.x >> 5);
    int stride = g_stride;

    float4 gg0 = ((const float4*)gamma)[lane];
    float4 gg1 = ((const float4*)gamma)[lane + 32];
    float4 bb0 = ((const float4*)beta )[lane];
    float4 bb1 = ((const float4*)beta )[lane + 32];

    int ntiles = (ntok + 31) >> 5;
    for (int tile = warp; tile < ntiles; tile += nwarp) {
        int t0 = tile << 5;
        int nt = min(32, ntok - t0);

        // Coalesced per-lane index loads (lane j -> token t0+j),
        // premultiplied to uint4 row offsets (32 uint4 per row).
        int a0 = 0, a1 = 0, a2 = 0, a3 = 0, a4 = 0;
        if (lane < nt) {
            size_t ti = (size_t)(t0 + lane) * (size_t)stride;
            a0 = (        (i0[ti] << 2) + i5[ti]) * 32;   // etrc = et*4 + rc
            a1 = ( 256 +  i1[ti])                 * 32;   // fc
            a2 = ( 512 +  i2[ti])                 * 32;   // sc
            a3 = (1024 +  i3[ti])                 * 32;   // of
            a4 = (1152 +  i4[ti])                 * 32;   // tt
        }

        for (int j = 0; j < nt; j++) {
            int b0 = __shfl_sync(~0u, a0, j) + lane;
            int b1 = __shfl_sync(~0u, a1, j) + lane;
            int b2 = __shfl_sync(~0u, a2, j) + lane;
            int b3 = __shfl_sync(~0u, a3, j) + lane;
            int b4 = __shfl_sync(~0u, a4, j) + lane;

            // 5 gathers (one uint4 each), issued up front for MLP.
            uint4 q0 = Pu[b0];
            uint4 q1 = Pu[b1];
            uint4 q2 = Pu[b2];
            uint4 q3 = Pu[b3];
            uint4 q4 = Pu[b4];

            // fp16 accumulation: 4 half2 slots x 4 adds
            __half2 h0 = __hadd2(h2(q0.x), h2(q1.x));
            __half2 h1 = __hadd2(h2(q0.y), h2(q1.y));
            __half2 h2v= __hadd2(h2(q0.z), h2(q1.z));
            __half2 h3 = __hadd2(h2(q0.w), h2(q1.w));
            h0 = __hadd2(h0, h2(q2.x));  h1 = __hadd2(h1, h2(q2.y));
            h2v= __hadd2(h2v,h2(q2.z));  h3 = __hadd2(h3, h2(q2.w));
            h0 = __hadd2(h0, h2(q3.x));  h1 = __hadd2(h1, h2(q3.y));
            h2v= __hadd2(h2v,h2(q3.z));  h3 = __hadd2(h3, h2(q3.w));
            h0 = __hadd2(h0, h2(q4.x));  h1 = __hadd2(h1, h2(q4.y));
            h2v= __hadd2(h2v,h2(q4.z));  h3 = __hadd2(h3, h2(q4.w));

            // convert once to fp32
            float2 f0 = __half22float2(h0);
            float2 f1 = __half22float2(h1);
            float2 f2 = __half22float2(h2v);
            float2 f3 = __half22float2(h3);
            float4 z0 = make_float4(f0.x, f0.y, f1.x, f1.y);   // cols 4l..4l+3
            float4 z1 = make_float4(f2.x, f2.y, f3.x, f3.y);   // cols 128+4l..

            float s  = z0.x + z0.y + z0.z + z0.w + z1.x + z1.y + z1.z + z1.w;
            float sq = z0.x*z0.x + z0.y*z0.y + z0.z*z0.z + z0.w*z0.w
                     + z1.x*z1.x + z1.y*z1.y + z1.z*z1.z + z1.w*z1.w;
            #pragma unroll
            for (int o = 16; o > 0; o >>= 1) {
                s  += __shfl_xor_sync(~0u, s,  o);
                sq += __shfl_xor_sync(~0u, sq, o);
            }
            float mu   = s * (1.0f / 256.0f);
            float var  = sq * (1.0f / 256.0f) - mu * mu;
            float rstd = rsqrtf(var + EPS_LN);

            float4* op = (float4*)(out + (size_t)(t0 + j) * DOUT);
            float4 o0, o1;
            o0.x = (z0.x - mu) * rstd * gg0.x + bb0.x;
            o0.y = (z0.y - mu) * rstd * gg0.y + bb0.y;
            o0.z = (z0.z - mu) * rstd * gg0.z + bb0.z;
            o0.w = (z0.w - mu) * rstd * gg0.w + bb0.w;
            o1.x = (z1.x - mu) * rstd * gg1.x + bb1.x;
            o1.y = (z1.y - mu) * rstd * gg1.y + bb1.y;
            o1.z = (z1.z - mu) * rstd * gg1.z + bb1.z;
            o1.w = (z1.w - mu) * rstd * gg1.w + bb1.w;
            __stcs(op + lane,      o0);   // streaming store: keep L2 for the table
            __stcs(op + 32 + lane, o1);
        }
    }
}

// ---------------------------------------------------------------------------
extern "C" void kernel_launch(void* const* d_in, const int* in_sizes, int n_in,
                              void* d_out, int out_size) {
    // Inputs (metadata order):
    // 0..5 : event_type, fault_class, syscall_class, opcode_family,
    //        transition_type, result_class        [B,S] integer
    // 6..11: E_et[64,16] E_fc[256,16] E_sc[512,16] E_of[128,16] E_tt[64,16] E_rc[4,16]
    // 12: W[256,96]  13: b[256]  14: gamma[256]  15: beta[256]
    int ntok = in_sizes[0];

    k_detect<<<1, 256>>>((const int*)d_in[0]);
    k_scale<<<1, 1024>>>((const float*)d_in[12]);
    k_build<<<NROWS, 256>>>((const float*)d_in[12], (const float*)d_in[13],
                            (const float*)d_in[6], (const float*)d_in[7],
                            (const float*)d_in[8], (const float*)d_in[9],
                            (const float*)d_in[10], (const float*)d_in[11]);
    k_main<<<2048, 256>>>((const int*)d_in[0], (const int*)d_in[1],
                          (const int*)d_in[2], (const int*)d_in[3],
                          (const int*)d_in[4], (const int*)d_in[5],
                          (const float*)d_in[14], (const float*)d_in[15],
                          (float*)d_out, ntok);
}